// round 9
// baseline (speedup 1.0000x reference)
#include <cuda_runtime.h>
#include <cuda_fp16.h>
#include <cstdint>

// ---------------- problem dims ----------------
#define MTOK 32768
#define DD   1024
#define NQKV 3072
#define NT2  16            // K=1024 / BK=64 k-tiles

// ---------------- scratch (device globals) ----------------
__device__ __half g_xh   [(size_t)MTOK * DD];     // fp16 x
__device__ __half g_wqkvh[3 * DD * DD];           // packed wq|wk|wv fp16
__device__ __half g_woh  [DD * DD];               // fp16 wo
__device__ __half g_qkvh [(size_t)MTOK * NQKV];   // packed q|k|v fp16
__device__ __half g_ctxh [(size_t)MTOK * DD];     // fp16 context

// ---------------- helpers ----------------
__device__ __forceinline__ uint32_t pack_h2(float a, float b) {
    __half2 h = __floats2half2_rn(a, b);
    return *(uint32_t*)&h;
}

__global__ void f2h_kernel(uint4* __restrict__ dst, const float4* __restrict__ src, int n8) {
    int i = blockIdx.x * blockDim.x + threadIdx.x;
    if (i < n8) {
        float4 a = src[2 * i], b = src[2 * i + 1];
        uint4 o;
        o.x = pack_h2(a.x, a.y); o.y = pack_h2(a.z, a.w);
        o.z = pack_h2(b.x, b.y); o.w = pack_h2(b.z, b.w);
        dst[i] = o;
    }
}

__global__ void f2h3_kernel(uint4* __restrict__ dst, const float4* __restrict__ s0,
                            const float4* __restrict__ s1, const float4* __restrict__ s2) {
    int i = blockIdx.x * blockDim.x + threadIdx.x;   // < 3*131072
    const float4* s = (i < 131072) ? s0 : (i < 262144 ? s1 : s2);
    int j = (i & 131071) * 2;
    float4 a = s[j], b = s[j + 1];
    uint4 o;
    o.x = pack_h2(a.x, a.y); o.y = pack_h2(a.z, a.w);
    o.z = pack_h2(b.x, b.y); o.w = pack_h2(b.z, b.w);
    dst[i] = o;
}

// ---------------- fp16 GEMM: 128x128 tile, BK=64, 4 warps (2x2), warp tile 64x64 ----------------
// SW128 smem rows (128B = 64 halves), 3-stage cp.async ring, 2 CTAs/SM.
#define STAGE_BYTES 32768    // A 16KB + B 16KB

__device__ __forceinline__ void cp_async16(uint32_t smem, const void* gmem) {
    asm volatile("cp.async.cg.shared.global [%0], [%1], 16;\n" :: "r"(smem), "l"(gmem));
}
__device__ __forceinline__ void ldsm4(uint32_t* r, uint32_t addr) {
    asm volatile("ldmatrix.sync.aligned.m8n8.x4.shared.b16 {%0,%1,%2,%3}, [%4];"
                 : "=r"(r[0]), "=r"(r[1]), "=r"(r[2]), "=r"(r[3]) : "r"(addr));
}

__global__ __launch_bounds__(128, 2)
void gemm_f16(const __half* __restrict__ A, const __half* __restrict__ W,
              const float* __restrict__ b0, const float* __restrict__ b1,
              const float* __restrict__ b2, float* __restrict__ Cf,
              __half* __restrict__ Ch, int ldc)
{
    extern __shared__ char smraw[];
    uint32_t sm_u = ((uint32_t)__cvta_generic_to_shared(smraw) + 1023u) & ~1023u;

    const int tid  = threadIdx.x;
    const int warp = tid >> 5, lane = tid & 31;
    const int wm   = warp >> 1, wn = warp & 1;     // 2(m) x 2(n)
    const int lt   = lane & 3,  lr = lane >> 2;
    const int K    = DD;

    // ---- loader: thread t owns A row t and B row t (full 128B rows, 8 chunks)
    const __half* aBase = A + (size_t)(blockIdx.y * 128 + tid) * K;
    const __half* bBase = W + (size_t)(blockIdx.x * 128 + tid) * K;
    const uint32_t rowoff = (uint32_t)tid * 128u;
    const uint32_t t7 = (uint32_t)(tid & 7);

    auto load_stage = [&](int kt, int s) {
        uint32_t st = sm_u + (uint32_t)s * STAGE_BYTES;
        const __half* ap = aBase + kt * 64;
        const __half* bp = bBase + kt * 64;
        #pragma unroll
        for (int c = 0; c < 8; c++) {
            uint32_t d = rowoff + (((uint32_t)c ^ t7) << 4);
            cp_async16(st + d,           ap + c * 8);
            cp_async16(st + 16384u + d,  bp + c * 8);
        }
        asm volatile("cp.async.commit_group;");
    };

    // ---- ldmatrix per-lane bases (round-8-verified lane mappings) ----
    // A: rlA rows, cA = 16B-block; swizzled chunk = (cA + 2kk) ^ (lane&7)
    const int rlA = (lane & 7) | (((lane >> 3) & 1) << 3);
    const int cA  = (lane >> 4) & 1;
    const uint32_t baseA = (uint32_t)((wm * 64 + rlA) * 128)
                         + (((uint32_t)cA ^ (uint32_t)(lane & 7)) << 4);
    // B: rlB rows, cB block
    const int rlB = (lane & 7) | (((lane >> 4) & 1) << 3);
    const int cB  = (lane >> 3) & 1;
    const uint32_t baseB = 16384u + (uint32_t)((wn * 64 + rlB) * 128)
                         + (((uint32_t)cB ^ (uint32_t)(lane & 7)) << 4);

    load_stage(0, 0);
    load_stage(1, 1);

    float acc[4][8][4];
    #pragma unroll
    for (int a = 0; a < 4; a++)
        #pragma unroll
        for (int b = 0; b < 8; b++)
            #pragma unroll
            for (int c = 0; c < 4; c++) acc[a][b][c] = 0.f;

    for (int kt = 0; kt < NT2; kt++) {
        if (kt + 1 < NT2) asm volatile("cp.async.wait_group 1;");
        else              asm volatile("cp.async.wait_group 0;");
        __syncthreads();
        if (kt + 2 < NT2) load_stage(kt + 2, (kt + 2) % 3);

        const uint32_t st = sm_u + (uint32_t)(kt % 3) * STAGE_BYTES;

        #pragma unroll
        for (int kk = 0; kk < 4; kk++) {
            const uint32_t kx = (uint32_t)kk << 5;
            uint32_t a[4][4], b[4][4];
            #pragma unroll
            for (int mf = 0; mf < 4; mf++)
                ldsm4(a[mf], (st + baseA + (uint32_t)mf * 2048u) ^ kx);
            #pragma unroll
            for (int pr = 0; pr < 4; pr++)
                ldsm4(b[pr], (st + baseB + (uint32_t)pr * 2048u) ^ kx);

            #pragma unroll
            for (int mf = 0; mf < 4; mf++)
                #pragma unroll
                for (int nf = 0; nf < 8; nf++) {
                    const uint32_t bb0 = b[nf >> 1][(nf & 1) * 2];
                    const uint32_t bb1 = b[nf >> 1][(nf & 1) * 2 + 1];
                    asm volatile(
                        "mma.sync.aligned.m16n8k16.row.col.f32.f16.f16.f32 "
                        "{%0,%1,%2,%3}, {%4,%5,%6,%7}, {%8,%9}, {%0,%1,%2,%3};"
                        : "+f"(acc[mf][nf][0]), "+f"(acc[mf][nf][1]),
                          "+f"(acc[mf][nf][2]), "+f"(acc[mf][nf][3])
                        : "r"(a[mf][0]), "r"(a[mf][1]), "r"(a[mf][2]), "r"(a[mf][3]),
                          "r"(bb0), "r"(bb1));
                }
        }
    }

    // ---- epilogue: region-selected bias; fp16 or fp32 output ----
    const int colbase = blockIdx.x * 128;
    const float* bias = (colbase < 1024) ? b0 : (colbase < 2048 ? b1 : b2);
    const int bofs    = colbase & 1023;
    const int crow0   = blockIdx.y * 128 + wm * 64 + lr;
    const int ccl     = wn * 64 + lt * 2;
    #pragma unroll
    for (int mf = 0; mf < 4; mf++) {
        #pragma unroll
        for (int nf = 0; nf < 8; nf++) {
            int r  = crow0 + mf * 16;
            int cl = ccl + nf * 8;
            float bb0 = __ldg(bias + bofs + cl), bb1 = __ldg(bias + bofs + cl + 1);
            float v00 = acc[mf][nf][0] + bb0, v01 = acc[mf][nf][1] + bb1;
            float v10 = acc[mf][nf][2] + bb0, v11 = acc[mf][nf][3] + bb1;
            if (Ch) {
                *(uint32_t*)&Ch[(size_t)r * ldc + colbase + cl]       = pack_h2(v00, v01);
                *(uint32_t*)&Ch[(size_t)(r + 8) * ldc + colbase + cl] = pack_h2(v10, v11);
            } else {
                *(float2*)&Cf[(size_t)r * ldc + colbase + cl]       = make_float2(v00, v01);
                *(float2*)&Cf[(size_t)(r + 8) * ldc + colbase + cl] = make_float2(v10, v11);
            }
        }
    }
}

// ---------------- per-token attention (softmax over HEAD axis), fp16 I/O ----------------
__global__ void attn_kernel(const __half* __restrict__ QKV, __half* __restrict__ CTX)
{
    __shared__ float sq[16][68], sk[16][68], sv[16][68], sp[16][17];
    const int t   = blockIdx.x;
    const int tid = threadIdx.x;
    const int h   = tid >> 4;
    const int g   = tid & 15;

    const uint2* r2 = (const uint2*)(QKV + (size_t)t * NQKV);
    auto to4 = [](uint2 u, float* d) {
        __half2 h0 = *(__half2*)&u.x, h1 = *(__half2*)&u.y;
        float2 f0 = __half22float2(h0), f1 = __half22float2(h1);
        d[0] = f0.x; d[1] = f0.y; d[2] = f1.x; d[3] = f1.y;
    };
    float tmp[4];
    to4(r2[tid],       tmp); *(float4*)&sq[h][g * 4] = *(float4*)tmp;
    to4(r2[256 + tid], tmp); *(float4*)&sk[h][g * 4] = *(float4*)tmp;
    to4(r2[512 + tid], tmp); *(float4*)&sv[h][g * 4] = *(float4*)tmp;
    __syncthreads();

    float s = 0.f;
    #pragma unroll
    for (int d = 0; d < 16; d++) {
        float4 qa = *(const float4*)&sq[h][d * 4];
        float4 ka = *(const float4*)&sk[g][d * 4];
        s += qa.x * ka.x + qa.y * ka.y + qa.z * ka.z + qa.w * ka.w;
    }
    s *= 0.125f;

    float m = s;
    #pragma unroll
    for (int o = 8; o; o >>= 1) m = fmaxf(m, __shfl_xor_sync(0xffffffffu, m, o));
    float e = __expf(s - m);
    float sum = e;
    #pragma unroll
    for (int o = 8; o; o >>= 1) sum += __shfl_xor_sync(0xffffffffu, sum, o);
    sp[h][g] = e / sum;
    __syncthreads();

    float4 acc = make_float4(0.f, 0.f, 0.f, 0.f);
    #pragma unroll
    for (int gg = 0; gg < 16; gg++) {
        float p   = sp[h][gg];
        float4 va = *(const float4*)&sv[gg][g * 4];
        acc.x += p * va.x; acc.y += p * va.y;
        acc.z += p * va.z; acc.w += p * va.w;
    }
    uint2 o;
    o.x = pack_h2(acc.x, acc.y);
    o.y = pack_h2(acc.z, acc.w);
    ((uint2*)(CTX + (size_t)t * DD))[tid] = o;
}

// ---------------- launch (6 launches; #6 = O-GEMM for ncu -s5 -c1) ----------------
extern "C" void kernel_launch(void* const* d_in, const int* in_sizes, int n_in,
                              void* d_out, int out_size)
{
    const float* x  = (const float*)d_in[0];
    const float* wq = (const float*)d_in[1];
    const float* bq = (const float*)d_in[2];
    const float* wk = (const float*)d_in[3];
    const float* bk = (const float*)d_in[4];
    const float* wv = (const float*)d_in[5];
    const float* bv = (const float*)d_in[6];
    const float* wo = (const float*)d_in[7];
    const float* bo = (const float*)d_in[8];
    float* out = (float*)d_out;

    __half *p_xh, *p_wqkvh, *p_woh, *p_qkvh, *p_ctxh;
    cudaGetSymbolAddress((void**)&p_xh,    g_xh);
    cudaGetSymbolAddress((void**)&p_wqkvh, g_wqkvh);
    cudaGetSymbolAddress((void**)&p_woh,   g_woh);
    cudaGetSymbolAddress((void**)&p_qkvh,  g_qkvh);
    cudaGetSymbolAddress((void**)&p_ctxh,  g_ctxh);

    const int smem = 3 * STAGE_BYTES + 1024;   // 99328 B
    cudaFuncSetAttribute(gemm_f16, cudaFuncAttributeMaxDynamicSharedMemorySize, smem);

    // 1) x -> fp16
    {
        int n8 = (int)((size_t)MTOK * DD / 8);
        f2h_kernel<<<(n8 + 255) / 256, 256>>>((uint4*)p_xh, (const float4*)x, n8);
    }
    // 2) wq|wk|wv -> packed fp16
    f2h3_kernel<<<(3 * 131072 + 255) / 256, 256>>>(
        (uint4*)p_wqkvh, (const float4*)wq, (const float4*)wk, (const float4*)wv);
    // 3) wo -> fp16
    {
        int n8 = DD * DD / 8;
        f2h_kernel<<<(n8 + 255) / 256, 256>>>((uint4*)p_woh, (const float4*)wo, n8);
    }

    // 4) fused QKV projection: [32768,1024] @ [3072,1024]^T -> fp16
    gemm_f16<<<dim3(NQKV / 128, MTOK / 128), 128, smem>>>(
        p_xh, p_wqkvh, bq, bk, bv, nullptr, p_qkvh, NQKV);

    // 5) per-token head-softmax attention (fp16 in/out)
    attn_kernel<<<MTOK, 256>>>(p_qkvh, p_ctxh);

    // 6) output projection -> fp32 out
    gemm_f16<<<dim3(DD / 128, MTOK / 128), 128, smem>>>(
        p_ctxh, p_woh, bo, bo, bo, out, nullptr, DD);
}

// round 11
// speedup vs baseline: 1.4715x; 1.4715x over previous
#include <cuda_runtime.h>
#include <cuda_fp16.h>
#include <cstdint>

// ---------------- problem dims ----------------
#define MTOK 32768
#define DD   1024
#define NQKV 3072
#define NT2  16            // K=1024 / BK=64 k-tiles

// ---------------- scratch (device globals) ----------------
__device__ __half g_xh   [(size_t)MTOK * DD];     // fp16 x
__device__ __half g_wqkvh[3 * DD * DD];           // packed wq|wk|wv fp16
__device__ __half g_woh  [DD * DD];               // fp16 wo
__device__ __half g_qkvh [(size_t)MTOK * NQKV];   // packed q|k|v fp16
__device__ __half g_ctxh [(size_t)MTOK * DD];     // fp16 context

// ---------------- helpers ----------------
__device__ __forceinline__ uint32_t pack_h2(float a, float b) {
    __half2 h = __floats2half2_rn(a, b);
    return *(uint32_t*)&h;
}

__global__ void f2h_kernel(uint4* __restrict__ dst, const float4* __restrict__ src, int n8) {
    int i = blockIdx.x * blockDim.x + threadIdx.x;
    if (i < n8) {
        float4 a = src[2 * i], b = src[2 * i + 1];
        uint4 o;
        o.x = pack_h2(a.x, a.y); o.y = pack_h2(a.z, a.w);
        o.z = pack_h2(b.x, b.y); o.w = pack_h2(b.z, b.w);
        dst[i] = o;
    }
}

__global__ void f2h3_kernel(uint4* __restrict__ dst, const float4* __restrict__ s0,
                            const float4* __restrict__ s1, const float4* __restrict__ s2) {
    int i = blockIdx.x * blockDim.x + threadIdx.x;   // < 3*131072
    const float4* s = (i < 131072) ? s0 : (i < 262144 ? s1 : s2);
    int j = (i & 131071) * 2;
    float4 a = s[j], b = s[j + 1];
    uint4 o;
    o.x = pack_h2(a.x, a.y); o.y = pack_h2(a.z, a.w);
    o.z = pack_h2(b.x, b.y); o.w = pack_h2(b.z, b.w);
    dst[i] = o;
}

// ---------------- fp16 GEMM: 128x128 tile, BK=64, 8 warps (2m x 4n), warp 64x32 ----------------
// SW128 full-row swizzle (row=128B), 3-stage cp.async ring, 1 sync/iter, 2 CTAs/SM.
#define STAGE_BYTES 32768    // A 16KB + B 16KB

__device__ __forceinline__ void cp_async16(uint32_t smem, const void* gmem) {
    asm volatile("cp.async.cg.shared.global [%0], [%1], 16;\n" :: "r"(smem), "l"(gmem));
}
__device__ __forceinline__ void ldsm4(uint32_t* r, uint32_t addr) {
    asm volatile("ldmatrix.sync.aligned.m8n8.x4.shared.b16 {%0,%1,%2,%3}, [%4];"
                 : "=r"(r[0]), "=r"(r[1]), "=r"(r[2]), "=r"(r[3]) : "r"(addr));
}

__global__ __launch_bounds__(256, 2)
void gemm_f16(const __half* __restrict__ A, const __half* __restrict__ W,
              const float* __restrict__ b0, const float* __restrict__ b1,
              const float* __restrict__ b2, float* __restrict__ Cf,
              __half* __restrict__ Ch, int ldc)
{
    extern __shared__ char smraw[];
    uint32_t sm_u = ((uint32_t)__cvta_generic_to_shared(smraw) + 1023u) & ~1023u;

    const int tid  = threadIdx.x;
    const int warp = tid >> 5, lane = tid & 31;
    const int wm   = warp >> 2, wn = warp & 3;     // 2(m) x 4(n)
    const int lt   = lane & 3,  lr = lane >> 2;
    const int K    = DD;

    // ---- loader: thread t owns half a row (4 chunks) of A and of B
    const int rowt  = tid >> 1;                    // 0..127
    const int cbase = (tid & 1) * 4;               // chunk 0..3 or 4..7
    const __half* aBase = A + (size_t)(blockIdx.y * 128 + rowt) * K + cbase * 8;
    const __half* bBase = W + (size_t)(blockIdx.x * 128 + rowt) * K + cbase * 8;
    const uint32_t r7     = (uint32_t)(rowt & 7);
    const uint32_t rowoff = (uint32_t)rowt * 128u;

    auto load_stage = [&](int kt, int s) {
        uint32_t st = sm_u + (uint32_t)s * STAGE_BYTES;
        const __half* ap = aBase + kt * 64;
        const __half* bp = bBase + kt * 64;
        #pragma unroll
        for (int j = 0; j < 4; j++) {
            uint32_t d = rowoff + ((((uint32_t)(cbase + j)) ^ r7) << 4);
            cp_async16(st + d,           ap + j * 8);
            cp_async16(st + 16384u + d,  bp + j * 8);
        }
        asm volatile("cp.async.commit_group;");
    };

    // ---- ldmatrix per-lane bases (round-9-verified mappings) ----
    const int rlA = (lane & 7) | (((lane >> 3) & 1) << 3);
    const int cA  = (lane >> 4) & 1;
    const uint32_t baseA = (uint32_t)((wm * 64 + rlA) * 128)
                         + (((uint32_t)cA ^ (uint32_t)(lane & 7)) << 4);
    const int rlB = (lane & 7) | (((lane >> 4) & 1) << 3);
    const int cB  = (lane >> 3) & 1;
    const uint32_t baseB = 16384u + (uint32_t)((wn * 32 + rlB) * 128)
                         + (((uint32_t)cB ^ (uint32_t)(lane & 7)) << 4);

    load_stage(0, 0);
    load_stage(1, 1);

    float acc[4][4][4];
    #pragma unroll
    for (int a = 0; a < 4; a++)
        #pragma unroll
        for (int b = 0; b < 4; b++)
            #pragma unroll
            for (int c = 0; c < 4; c++) acc[a][b][c] = 0.f;

    for (int kt = 0; kt < NT2; kt++) {
        if (kt + 1 < NT2) asm volatile("cp.async.wait_group 1;");
        else              asm volatile("cp.async.wait_group 0;");
        __syncthreads();
        if (kt + 2 < NT2) load_stage(kt + 2, (kt + 2) % 3);

        const uint32_t st = sm_u + (uint32_t)(kt % 3) * STAGE_BYTES;

        #pragma unroll
        for (int kk = 0; kk < 4; kk++) {
            const uint32_t kx = (uint32_t)kk << 5;
            uint32_t a[4][4], b[2][4];
            #pragma unroll
            for (int mf = 0; mf < 4; mf++)
                ldsm4(a[mf], (st + baseA + (uint32_t)mf * 2048u) ^ kx);
            #pragma unroll
            for (int pr = 0; pr < 2; pr++)
                ldsm4(b[pr], (st + baseB + (uint32_t)pr * 2048u) ^ kx);

            #pragma unroll
            for (int mf = 0; mf < 4; mf++)
                #pragma unroll
                for (int nf = 0; nf < 4; nf++) {
                    const uint32_t bb0 = b[nf >> 1][(nf & 1) * 2];
                    const uint32_t bb1 = b[nf >> 1][(nf & 1) * 2 + 1];
                    asm volatile(
                        "mma.sync.aligned.m16n8k16.row.col.f32.f16.f16.f32 "
                        "{%0,%1,%2,%3}, {%4,%5,%6,%7}, {%8,%9}, {%0,%1,%2,%3};"
                        : "+f"(acc[mf][nf][0]), "+f"(acc[mf][nf][1]),
                          "+f"(acc[mf][nf][2]), "+f"(acc[mf][nf][3])
                        : "r"(a[mf][0]), "r"(a[mf][1]), "r"(a[mf][2]), "r"(a[mf][3]),
                          "r"(bb0), "r"(bb1));
                }
        }
    }

    // ---- epilogue: region-selected bias; fp16 or fp32 output ----
    const int colbase = blockIdx.x * 128;
    const float* bias = (colbase < 1024) ? b0 : (colbase < 2048 ? b1 : b2);
    const int bofs    = colbase & 1023;
    const int crow0   = blockIdx.y * 128 + wm * 64 + lr;
    const int ccl     = wn * 32 + lt * 2;
    #pragma unroll
    for (int mf = 0; mf < 4; mf++) {
        #pragma unroll
        for (int nf = 0; nf < 4; nf++) {
            int r  = crow0 + mf * 16;
            int cl = ccl + nf * 8;
            float bb0 = __ldg(bias + bofs + cl), bb1 = __ldg(bias + bofs + cl + 1);
            float v00 = acc[mf][nf][0] + bb0, v01 = acc[mf][nf][1] + bb1;
            float v10 = acc[mf][nf][2] + bb0, v11 = acc[mf][nf][3] + bb1;
            if (Ch) {
                *(uint32_t*)&Ch[(size_t)r * ldc + colbase + cl]       = pack_h2(v00, v01);
                *(uint32_t*)&Ch[(size_t)(r + 8) * ldc + colbase + cl] = pack_h2(v10, v11);
            } else {
                *(float2*)&Cf[(size_t)r * ldc + colbase + cl]       = make_float2(v00, v01);
                *(float2*)&Cf[(size_t)(r + 8) * ldc + colbase + cl] = make_float2(v10, v11);
            }
        }
    }
}

// ---------------- attention: warp-per-token, softmax over HEAD axis ----------------
// 8 tokens / 256-thread block. k,v converted to fp32 in smem (slot-permuted,
// stride 68 floats); q in registers. No __syncthreads.
#define KV_STRIDE 68
#define WARP_SMEM (2 * 16 * KV_STRIDE)       // floats per warp (k then v)

__global__ __launch_bounds__(256, 2)
void attn_kernel(const __half* __restrict__ QKV, __half* __restrict__ CTX)
{
    extern __shared__ float smf[];
    const int wid  = threadIdx.x >> 5;
    const int lane = threadIdx.x & 31;
    const size_t t = (size_t)blockIdx.x * 8 + wid;
    const __half* base = QKV + t * NQKV;

    float* skw = smf + wid * WARP_SMEM;          // k: 16 slots x 68
    float* svw = skw + 16 * KV_STRIDE;           // v: 16 slots x 68

    // ---- load + convert k, v into smem (4 uint4 per lane per matrix)
    #pragma unroll
    for (int m = 0; m < 2; m++) {                // 0=k, 1=v
        const uint4* src = (const uint4*)(base + 1024 + m * 1024);
        float* dstm = m ? svw : skw;
        #pragma unroll
        for (int j = 0; j < 4; j++) {
            int idx = lane + 32 * j;             // uint4 index, 0..127
            uint4 r = src[idx];
            int row  = idx >> 3;                 // 0..15
            int col  = (idx & 7) * 8;            // 0..56
            int slot = ((row & 7) << 1) | (row >> 3);
            float* d = dstm + slot * KV_STRIDE + col;
            float2 f0 = __half22float2(*(__half2*)&r.x);
            float2 f1 = __half22float2(*(__half2*)&r.y);
            float2 f2 = __half22float2(*(__half2*)&r.z);
            float2 f3 = __half22float2(*(__half2*)&r.w);
            *(float4*)(d)     = make_float4(f0.x, f0.y, f1.x, f1.y);
            *(float4*)(d + 4) = make_float4(f2.x, f2.y, f3.x, f3.y);
        }
    }

    // ---- load q row (h = lane>>1) into fp32 registers
    const int h = lane >> 1;
    float qf[64];
    {
        const uint4* qsrc = (const uint4*)(base + h * 64);
        #pragma unroll
        for (int u = 0; u < 8; u++) {
            uint4 r = qsrc[u];
            float2 f0 = __half22float2(*(__half2*)&r.x);
            float2 f1 = __half22float2(*(__half2*)&r.y);
            float2 f2 = __half22float2(*(__half2*)&r.z);
            float2 f3 = __half22float2(*(__half2*)&r.w);
            qf[u*8+0]=f0.x; qf[u*8+1]=f0.y; qf[u*8+2]=f1.x; qf[u*8+3]=f1.y;
            qf[u*8+4]=f2.x; qf[u*8+5]=f2.y; qf[u*8+6]=f3.x; qf[u*8+7]=f3.y;
        }
    }
    __syncwarp();

    // ---- scores: lane handles g = (lane&1)*8 + j, j=0..7; slot = 2j + (lane&1)
    float p[8];
    {
        float sc[8];
        #pragma unroll
        for (int j = 0; j < 8; j++) {
            const float* kr = skw + (2 * j + (lane & 1)) * KV_STRIDE;
            float s = 0.f;
            #pragma unroll
            for (int i = 0; i < 16; i++) {
                float4 k4 = *(const float4*)(kr + i * 4);
                s += qf[4*i] * k4.x + qf[4*i+1] * k4.y
                   + qf[4*i+2] * k4.z + qf[4*i+3] * k4.w;
            }
            sc[j] = s * 0.125f;
        }
        float mx = sc[0];
        #pragma unroll
        for (int j = 1; j < 8; j++) mx = fmaxf(mx, sc[j]);
        mx = fmaxf(mx, __shfl_xor_sync(0xffffffffu, mx, 1));
        float sum = 0.f;
        #pragma unroll
        for (int j = 0; j < 8; j++) { p[j] = __expf(sc[j] - mx); sum += p[j]; }
        sum += __shfl_xor_sync(0xffffffffu, sum, 1);
        float inv = __frcp_rn(sum);
        #pragma unroll
        for (int j = 0; j < 8; j++) p[j] *= inv;
    }

    // ---- full p[16] for this h via pair exchange
    float pg[16];
    {
        #pragma unroll
        for (int j = 0; j < 8; j++) {
            float po = __shfl_xor_sync(0xffffffffu, p[j], 1);
            if ((lane & 1) == 0) { pg[j] = p[j];  pg[8 + j] = po;   }
            else                 { pg[j] = po;    pg[8 + j] = p[j]; }
        }
    }

    // ---- ctx: lane covers d = (lane&1)*4 + 8m, m=0..7 (4 d's each)
    float acc[32];
    #pragma unroll
    for (int i = 0; i < 32; i++) acc[i] = 0.f;
    const int dofs = (lane & 1) * 4;
    #pragma unroll
    for (int g = 0; g < 16; g++) {
        const float* vr = svw + (((g & 7) << 1) | (g >> 3)) * KV_STRIDE + dofs;
        float w = pg[g];
        #pragma unroll
        for (int m = 0; m < 8; m++) {
            float4 v4 = *(const float4*)(vr + m * 8);
            acc[4*m+0] += w * v4.x; acc[4*m+1] += w * v4.y;
            acc[4*m+2] += w * v4.z; acc[4*m+3] += w * v4.w;
        }
    }

    // ---- store ctx fp16
    __half* out = CTX + t * DD + h * 64 + dofs;
    #pragma unroll
    for (int m = 0; m < 8; m++) {
        uint2 o;
        o.x = pack_h2(acc[4*m+0], acc[4*m+1]);
        o.y = pack_h2(acc[4*m+2], acc[4*m+3]);
        *(uint2*)(out + m * 8) = o;
    }
}

// ---------------- launch (6 launches; #6 = O-GEMM for ncu -s5 -c1) ----------------
extern "C" void kernel_launch(void* const* d_in, const int* in_sizes, int n_in,
                              void* d_out, int out_size)
{
    const float* x  = (const float*)d_in[0];
    const float* wq = (const float*)d_in[1];
    const float* bq = (const float*)d_in[2];
    const float* wk = (const float*)d_in[3];
    const float* bk = (const float*)d_in[4];
    const float* wv = (const float*)d_in[5];
    const float* bv = (const float*)d_in[6];
    const float* wo = (const float*)d_in[7];
    const float* bo = (const float*)d_in[8];
    float* out = (float*)d_out;

    __half *p_xh, *p_wqkvh, *p_woh, *p_qkvh, *p_ctxh;
    cudaGetSymbolAddress((void**)&p_xh,    g_xh);
    cudaGetSymbolAddress((void**)&p_wqkvh, g_wqkvh);
    cudaGetSymbolAddress((void**)&p_woh,   g_woh);
    cudaGetSymbolAddress((void**)&p_qkvh,  g_qkvh);
    cudaGetSymbolAddress((void**)&p_ctxh,  g_ctxh);

    const int gsmem = 3 * STAGE_BYTES + 1024;            // 99328 B
    cudaFuncSetAttribute(gemm_f16, cudaFuncAttributeMaxDynamicSharedMemorySize, gsmem);
    const int asmem = 8 * WARP_SMEM * (int)sizeof(float); // 69632 B
    cudaFuncSetAttribute(attn_kernel, cudaFuncAttributeMaxDynamicSharedMemorySize, asmem);

    // 1) x -> fp16
    {
        int n8 = (int)((size_t)MTOK * DD / 8);
        f2h_kernel<<<(n8 + 255) / 256, 256>>>((uint4*)p_xh, (const float4*)x, n8);
    }
    // 2) wq|wk|wv -> packed fp16
    f2h3_kernel<<<(3 * 131072 + 255) / 256, 256>>>(
        (uint4*)p_wqkvh, (const float4*)wq, (const float4*)wk, (const float4*)wv);
    // 3) wo -> fp16
    {
        int n8 = DD * DD / 8;
        f2h_kernel<<<(n8 + 255) / 256, 256>>>((uint4*)p_woh, (const float4*)wo, n8);
    }

    // 4) fused QKV projection: [32768,1024] @ [3072,1024]^T -> fp16
    gemm_f16<<<dim3(NQKV / 128, MTOK / 128), 256, gsmem>>>(
        p_xh, p_wqkvh, bq, bk, bv, nullptr, p_qkvh, NQKV);

    // 5) warp-per-token head-softmax attention
    attn_kernel<<<MTOK / 8, 256, asmem>>>(p_qkvh, p_ctxh);

    // 6) output projection -> fp32 out
    gemm_f16<<<dim3(DD / 128, MTOK / 128), 256, gsmem>>>(
        p_ctxh, p_woh, bo, bo, bo, out, nullptr, DD);
}

// round 16
// speedup vs baseline: 1.8851x; 1.2811x over previous
#include <cuda_runtime.h>
#include <cuda_fp16.h>
#include <cstdint>

// ---------------- problem dims ----------------
#define MTOK 32768
#define DD   1024
#define NQKV 3072
#define NT2  16            // K=1024 / BK=64 k-tiles

// ---------------- scratch (device globals) ----------------
__device__ __half g_xh   [(size_t)MTOK * DD];     // fp16 x
__device__ __half g_wqkvh[3 * DD * DD];           // packed wq|wk|wv fp16
__device__ __half g_woh  [DD * DD];               // fp16 wo
__device__ __half g_qkvh [(size_t)MTOK * NQKV];   // packed q|k|v fp16
__device__ __half g_ctxh [(size_t)MTOK * DD];     // fp16 context

// ---------------- helpers ----------------
__device__ __forceinline__ uint32_t pack_h2(float a, float b) {
    __half2 h = __floats2half2_rn(a, b);
    return *(uint32_t*)&h;
}

__global__ void f2h_kernel(uint4* __restrict__ dst, const float4* __restrict__ src, int n8) {
    int i = blockIdx.x * blockDim.x + threadIdx.x;
    if (i < n8) {
        float4 a = src[2 * i], b = src[2 * i + 1];
        uint4 o;
        o.x = pack_h2(a.x, a.y); o.y = pack_h2(a.z, a.w);
        o.z = pack_h2(b.x, b.y); o.w = pack_h2(b.z, b.w);
        dst[i] = o;
    }
}

__global__ void f2h3_kernel(uint4* __restrict__ dst, const float4* __restrict__ s0,
                            const float4* __restrict__ s1, const float4* __restrict__ s2) {
    int i = blockIdx.x * blockDim.x + threadIdx.x;   // < 3*131072
    const float4* s = (i < 131072) ? s0 : (i < 262144 ? s1 : s2);
    int j = (i & 131071) * 2;
    float4 a = s[j], b = s[j + 1];
    uint4 o;
    o.x = pack_h2(a.x, a.y); o.y = pack_h2(a.z, a.w);
    o.z = pack_h2(b.x, b.y); o.w = pack_h2(b.z, b.w);
    dst[i] = o;
}

// ---------------- fp16 GEMM: 128x128 tile, BK=64, 8 warps (2m x 4n), warp 64x32 ----------------
// SW128 full-row swizzle, sector-aligned loader (lanes 0-7 = one 128B row),
// 3-stage cp.async ring, 1 sync/iter, 2 CTAs/SM.
#define STAGE_BYTES 32768    // A 16KB + B 16KB

__device__ __forceinline__ void cp_async16(uint32_t smem, const void* gmem) {
    asm volatile("cp.async.cg.shared.global [%0], [%1], 16;\n" :: "r"(smem), "l"(gmem));
}
__device__ __forceinline__ void ldsm4(uint32_t* r, uint32_t addr) {
    asm volatile("ldmatrix.sync.aligned.m8n8.x4.shared.b16 {%0,%1,%2,%3}, [%4];"
                 : "=r"(r[0]), "=r"(r[1]), "=r"(r[2]), "=r"(r[3]) : "r"(addr));
}

__global__ __launch_bounds__(256, 2)
void gemm_f16(const __half* __restrict__ A, const __half* __restrict__ W,
              const float* __restrict__ b0, const float* __restrict__ b1,
              const float* __restrict__ b2, float* __restrict__ Cf,
              __half* __restrict__ Ch, int ldc)
{
    extern __shared__ char smraw[];
    uint32_t sm_u = ((uint32_t)__cvta_generic_to_shared(smraw) + 1023u) & ~1023u;

    const int tid  = threadIdx.x;
    const int warp = tid >> 5, lane = tid & 31;
    const int wm   = warp >> 2, wn = warp & 3;     // 2(m) x 4(n)
    const int lt   = lane & 3,  lr = lane >> 2;
    const int K    = DD;

    // ---- sector-aligned loader: lanes 0-7 cover one full 128B row ----
    const int r0 = tid >> 3;                       // 0..31
    const int c  = tid & 7;                        // 16B chunk in row
    const __half* aBase = A + (size_t)(blockIdx.y * 128 + r0) * K + c * 8;
    const __half* bBase = W + (size_t)(blockIdx.x * 128 + r0) * K + c * 8;
    // swizzled chunk: (c ^ (row&7)); row&7 == r0&7 for all i (rows step by 32)
    const uint32_t doff = (uint32_t)(r0 * 128) + (((uint32_t)c ^ (uint32_t)(r0 & 7)) << 4);

    auto load_stage = [&](int kt, int s) {
        uint32_t st = sm_u + (uint32_t)s * STAGE_BYTES;
        const __half* ap = aBase + kt * 64;
        const __half* bp = bBase + kt * 64;
        #pragma unroll
        for (int i = 0; i < 4; i++) {
            cp_async16(st + doff + (uint32_t)i * 4096u,           ap + (size_t)i * 32 * K);
            cp_async16(st + 16384u + doff + (uint32_t)i * 4096u,  bp + (size_t)i * 32 * K);
        }
        asm volatile("cp.async.commit_group;");
    };

    // ---- ldmatrix per-lane bases (round-9/11-verified mappings) ----
    const int rlA = (lane & 7) | (((lane >> 3) & 1) << 3);
    const int cA  = (lane >> 4) & 1;
    const uint32_t baseA = (uint32_t)((wm * 64 + rlA) * 128)
                         + (((uint32_t)cA ^ (uint32_t)(lane & 7)) << 4);
    const int rlB = (lane & 7) | (((lane >> 4) & 1) << 3);
    const int cB  = (lane >> 3) & 1;
    const uint32_t baseB = 16384u + (uint32_t)((wn * 32 + rlB) * 128)
                         + (((uint32_t)cB ^ (uint32_t)(lane & 7)) << 4);

    load_stage(0, 0);
    load_stage(1, 1);

    float acc[4][4][4];
    #pragma unroll
    for (int a = 0; a < 4; a++)
        #pragma unroll
        for (int b = 0; b < 4; b++)
            #pragma unroll
            for (int c2 = 0; c2 < 4; c2++) acc[a][b][c2] = 0.f;

    for (int kt = 0; kt < NT2; kt++) {
        if (kt + 1 < NT2) asm volatile("cp.async.wait_group 1;");
        else              asm volatile("cp.async.wait_group 0;");
        __syncthreads();
        if (kt + 2 < NT2) load_stage(kt + 2, (kt + 2) % 3);

        const uint32_t st = sm_u + (uint32_t)(kt % 3) * STAGE_BYTES;

        #pragma unroll
        for (int kk = 0; kk < 4; kk++) {
            const uint32_t kx = (uint32_t)kk << 5;
            uint32_t a[4][4], b[2][4];
            #pragma unroll
            for (int mf = 0; mf < 4; mf++)
                ldsm4(a[mf], (st + baseA + (uint32_t)mf * 2048u) ^ kx);
            #pragma unroll
            for (int pr = 0; pr < 2; pr++)
                ldsm4(b[pr], (st + baseB + (uint32_t)pr * 2048u) ^ kx);

            #pragma unroll
            for (int mf = 0; mf < 4; mf++)
                #pragma unroll
                for (int nf = 0; nf < 4; nf++) {
                    const uint32_t bb0 = b[nf >> 1][(nf & 1) * 2];
                    const uint32_t bb1 = b[nf >> 1][(nf & 1) * 2 + 1];
                    asm volatile(
                        "mma.sync.aligned.m16n8k16.row.col.f32.f16.f16.f32 "
                        "{%0,%1,%2,%3}, {%4,%5,%6,%7}, {%8,%9}, {%0,%1,%2,%3};"
                        : "+f"(acc[mf][nf][0]), "+f"(acc[mf][nf][1]),
                          "+f"(acc[mf][nf][2]), "+f"(acc[mf][nf][3])
                        : "r"(a[mf][0]), "r"(a[mf][1]), "r"(a[mf][2]), "r"(a[mf][3]),
                          "r"(bb0), "r"(bb1));
                }
        }
    }

    // ---- epilogue: region-selected bias; fp16 or fp32 output ----
    const int colbase = blockIdx.x * 128;
    const float* bias = (colbase < 1024) ? b0 : (colbase < 2048 ? b1 : b2);
    const int bofs    = colbase & 1023;
    const int crow0   = blockIdx.y * 128 + wm * 64 + lr;
    const int ccl     = wn * 32 + lt * 2;
    #pragma unroll
    for (int mf = 0; mf < 4; mf++) {
        #pragma unroll
        for (int nf = 0; nf < 4; nf++) {
            int r  = crow0 + mf * 16;
            int cl = ccl + nf * 8;
            float bb0 = __ldg(bias + bofs + cl), bb1 = __ldg(bias + bofs + cl + 1);
            float v00 = acc[mf][nf][0] + bb0, v01 = acc[mf][nf][1] + bb1;
            float v10 = acc[mf][nf][2] + bb0, v11 = acc[mf][nf][3] + bb1;
            if (Ch) {
                *(uint32_t*)&Ch[(size_t)r * ldc + colbase + cl]       = pack_h2(v00, v01);
                *(uint32_t*)&Ch[(size_t)(r + 8) * ldc + colbase + cl] = pack_h2(v10, v11);
            } else {
                *(float2*)&Cf[(size_t)r * ldc + colbase + cl]       = make_float2(v00, v01);
                *(float2*)&Cf[(size_t)(r + 8) * ldc + colbase + cl] = make_float2(v10, v11);
            }
        }
    }
}

// ---------------- attention: warp-per-token, softmax over HEAD axis ----------------
#define KV_STRIDE 68
#define WARP_SMEM (2 * 16 * KV_STRIDE)       // floats per warp (k then v)

__global__ __launch_bounds__(256, 2)
void attn_kernel(const __half* __restrict__ QKV, __half* __restrict__ CTX)
{
    extern __shared__ float smf[];
    const int wid  = threadIdx.x >> 5;
    const int lane = threadIdx.x & 31;
    const size_t t = (size_t)blockIdx.x * 8 + wid;
    const __half* base = QKV + t * NQKV;

    float* skw = smf + wid * WARP_SMEM;
    float* svw = skw + 16 * KV_STRIDE;

    #pragma unroll
    for (int m = 0; m < 2; m++) {
        const uint4* src = (const uint4*)(base + 1024 + m * 1024);
        float* dstm = m ? svw : skw;
        #pragma unroll
        for (int j = 0; j < 4; j++) {
            int idx = lane + 32 * j;
            uint4 r = src[idx];
            int row  = idx >> 3;
            int col  = (idx & 7) * 8;
            int slot = ((row & 7) << 1) | (row >> 3);
            float* d = dstm + slot * KV_STRIDE + col;
            float2 f0 = __half22float2(*(__half2*)&r.x);
            float2 f1 = __half22float2(*(__half2*)&r.y);
            float2 f2 = __half22float2(*(__half2*)&r.z);
            float2 f3 = __half22float2(*(__half2*)&r.w);
            *(float4*)(d)     = make_float4(f0.x, f0.y, f1.x, f1.y);
            *(float4*)(d + 4) = make_float4(f2.x, f2.y, f3.x, f3.y);
        }
    }

    const int h = lane >> 1;
    float qf[64];
    {
        const uint4* qsrc = (const uint4*)(base + h * 64);
        #pragma unroll
        for (int u = 0; u < 8; u++) {
            uint4 r = qsrc[u];
            float2 f0 = __half22float2(*(__half2*)&r.x);
            float2 f1 = __half22float2(*(__half2*)&r.y);
            float2 f2 = __half22float2(*(__half2*)&r.z);
            float2 f3 = __half22float2(*(__half2*)&r.w);
            qf[u*8+0]=f0.x; qf[u*8+1]=f0.y; qf[u*8+2]=f1.x; qf[u*8+3]=f1.y;
            qf[u*8+4]=f2.x; qf[u*8+5]=f2.y; qf[u*8+6]=f3.x; qf[u*8+7]=f3.y;
        }
    }
    __syncwarp();

    float p[8];
    {
        float sc[8];
        #pragma unroll
        for (int j = 0; j < 8; j++) {
            const float* kr = skw + (2 * j + (lane & 1)) * KV_STRIDE;
            float s = 0.f;
            #pragma unroll
            for (int i = 0; i < 16; i++) {
                float4 k4 = *(const float4*)(kr + i * 4);
                s += qf[4*i] * k4.x + qf[4*i+1] * k4.y
                   + qf[4*i+2] * k4.z + qf[4*i+3] * k4.w;
            }
            sc[j] = s * 0.125f;
        }
        float mx = sc[0];
        #pragma unroll
        for (int j = 1; j < 8; j++) mx = fmaxf(mx, sc[j]);
        mx = fmaxf(mx, __shfl_xor_sync(0xffffffffu, mx, 1));
        float sum = 0.f;
        #pragma unroll
        for (int j = 0; j < 8; j++) { p[j] = __expf(sc[j] - mx); sum += p[j]; }
        sum += __shfl_xor_sync(0xffffffffu, sum, 1);
        float inv = __frcp_rn(sum);
        #pragma unroll
        for (int j = 0; j < 8; j++) p[j] *= inv;
    }

    float pg[16];
    {
        #pragma unroll
        for (int j = 0; j < 8; j++) {
            float po = __shfl_xor_sync(0xffffffffu, p[j], 1);
            if ((lane & 1) == 0) { pg[j] = p[j];  pg[8 + j] = po;   }
            else                 { pg[j] = po;    pg[8 + j] = p[j]; }
        }
    }

    float acc[32];
    #pragma unroll
    for (int i = 0; i < 32; i++) acc[i] = 0.f;
    const int dofs = (lane & 1) * 4;
    #pragma unroll
    for (int g = 0; g < 16; g++) {
        const float* vr = svw + (((g & 7) << 1) | (g >> 3)) * KV_STRIDE + dofs;
        float w = pg[g];
        #pragma unroll
        for (int m = 0; m < 8; m++) {
            float4 v4 = *(const float4*)(vr + m * 8);
            acc[4*m+0] += w * v4.x; acc[4*m+1] += w * v4.y;
            acc[4*m+2] += w * v4.z; acc[4*m+3] += w * v4.w;
        }
    }

    __half* out = CTX + t * DD + h * 64 + dofs;
    #pragma unroll
    for (int m = 0; m < 8; m++) {
        uint2 o;
        o.x = pack_h2(acc[4*m+0], acc[4*m+1]);
        o.y = pack_h2(acc[4*m+2], acc[4*m+3]);
        *(uint2*)(out + m * 8) = o;
    }
}

// ---------------- launch (6 launches; #6 = O-GEMM for ncu -s5 -c1) ----------------
extern "C" void kernel_launch(void* const* d_in, const int* in_sizes, int n_in,
                              void* d_out, int out_size)
{
    const float* x  = (const float*)d_in[0];
    const float* wq = (const float*)d_in[1];
    const float* bq = (const float*)d_in[2];
    const float* wk = (const float*)d_in[3];
    const float* bk = (const float*)d_in[4];
    const float* wv = (const float*)d_in[5];
    const float* bv = (const float*)d_in[6];
    const float* wo = (const float*)d_in[7];
    const float* bo = (const float*)d_in[8];
    float* out = (float*)d_out;

    __half *p_xh, *p_wqkvh, *p_woh, *p_qkvh, *p_ctxh;
    cudaGetSymbolAddress((void**)&p_xh,    g_xh);
    cudaGetSymbolAddress((void**)&p_wqkvh, g_wqkvh);
    cudaGetSymbolAddress((void**)&p_woh,   g_woh);
    cudaGetSymbolAddress((void**)&p_qkvh,  g_qkvh);
    cudaGetSymbolAddress((void**)&p_ctxh,  g_ctxh);

    const int gsmem = 3 * STAGE_BYTES + 1024;            // 99328 B
    cudaFuncSetAttribute(gemm_f16, cudaFuncAttributeMaxDynamicSharedMemorySize, gsmem);
    const int asmem = 8 * WARP_SMEM * (int)sizeof(float); // 69632 B
    cudaFuncSetAttribute(attn_kernel, cudaFuncAttributeMaxDynamicSharedMemorySize, asmem);

    // 1) x -> fp16
    {
        int n8 = (int)((size_t)MTOK * DD / 8);
        f2h_kernel<<<(n8 + 255) / 256, 256>>>((uint4*)p_xh, (const float4*)x, n8);
    }
    // 2) wq|wk|wv -> packed fp16
    f2h3_kernel<<<(3 * 131072 + 255) / 256, 256>>>(
        (uint4*)p_wqkvh, (const float4*)wq, (const float4*)wk, (const float4*)wv);
    // 3) wo -> fp16
    {
        int n8 = DD * DD / 8;
        f2h_kernel<<<(n8 + 255) / 256, 256>>>((uint4*)p_woh, (const float4*)wo, n8);
    }

    // 4) fused QKV projection: [32768,1024] @ [3072,1024]^T -> fp16
    gemm_f16<<<dim3(NQKV / 128, MTOK / 128), 256, gsmem>>>(
        p_xh, p_wqkvh, bq, bk, bv, nullptr, p_qkvh, NQKV);

    // 5) warp-per-token head-softmax attention
    attn_kernel<<<MTOK / 8, 256, asmem>>>(p_qkvh, p_ctxh);

    // 6) output projection -> fp32 out
    gemm_f16<<<dim3(DD / 128, MTOK / 128), 256, gsmem>>>(
        p_ctxh, p_woh, bo, bo, bo, out, nullptr, DD);
}